// round 2
// baseline (speedup 1.0000x reference)
#include <cuda_runtime.h>
#include <math.h>

#define NN 100000
#define EE 3200000
#define FIN 512
#define HH 256
#define CC 64
#define LL 8

// Scratch buffers (no cudaMalloc allowed)
__device__ float g_h[(size_t)NN * HH];
__device__ float g_x0[(size_t)NN * HH];
__device__ float g_agg[(size_t)NN * HH];

// ---------------------------------------------------------------------------
// Generic SGEMM: C = epilogue( c_acc * (scale_a*A) @ B  +  c_id * scale_a*A[i][j] + bias )
// A: [M,K] row-major, B: [K,Nc] row-major. BM=BN=128, BK=8, 256 threads, 8x8 micro.
// c_id term only valid when K == Nc (square layer GEMM).
// ---------------------------------------------------------------------------
__global__ __launch_bounds__(256, 2)
void sgemm_kernel(const float* __restrict__ A, const float* __restrict__ B,
                  const float* __restrict__ bias,
                  float* __restrict__ C, float* __restrict__ C2,
                  int M, int K, int Nc,
                  float scale_a, float c_acc, float c_id, int do_relu)
{
    __shared__ float As[8][128];
    __shared__ float Bs[8][128];

    const int tid = threadIdx.x;
    const int row0 = blockIdx.y * 128;
    const int col0 = blockIdx.x * 128;

    const int tx = tid & 15;   // 0..15  (N direction)
    const int ty = tid >> 4;   // 0..15  (M direction)

    float acc[8][8];
#pragma unroll
    for (int i = 0; i < 8; i++)
#pragma unroll
        for (int j = 0; j < 8; j++) acc[i][j] = 0.f;

    // A tile loads: 128 rows x 8 cols = 256 float4 (thread t -> row t/2, col4 (t&1)*4)
    const int a_row = tid >> 1;
    const int a_col4 = (tid & 1) * 4;
    // B tile loads: 8 rows x 128 cols = 256 float4 (thread t -> row t/32, col4 (t&31)*4)
    const int b_row = tid >> 5;
    const int b_col4 = (tid & 31) * 4;

    const bool a_valid = (row0 + a_row) < M;
    const float* Aptr = A + (size_t)(row0 + a_row) * K + a_col4;
    const float* Bptr = B + (size_t)b_row * Nc + col0 + b_col4;

    for (int k0 = 0; k0 < K; k0 += 8) {
        float4 av = a_valid ? *(const float4*)Aptr : make_float4(0.f, 0.f, 0.f, 0.f);
        float4 bv = *(const float4*)Bptr;
        As[a_col4 + 0][a_row] = av.x * scale_a;
        As[a_col4 + 1][a_row] = av.y * scale_a;
        As[a_col4 + 2][a_row] = av.z * scale_a;
        As[a_col4 + 3][a_row] = av.w * scale_a;
        *(float4*)&Bs[b_row][b_col4] = bv;
        __syncthreads();

#pragma unroll
        for (int kk = 0; kk < 8; kk++) {
            float areg[8], breg[8];
#pragma unroll
            for (int i = 0; i < 8; i++) areg[i] = As[kk][ty * 8 + i];
#pragma unroll
            for (int j = 0; j < 8; j++) breg[j] = Bs[kk][tx * 8 + j];
#pragma unroll
            for (int i = 0; i < 8; i++)
#pragma unroll
                for (int j = 0; j < 8; j++)
                    acc[i][j] += areg[i] * breg[j];
        }
        __syncthreads();
        Aptr += 8;
        Bptr += (size_t)8 * Nc;
    }

    // Epilogue
#pragma unroll
    for (int i = 0; i < 8; i++) {
        int r = row0 + ty * 8 + i;
        if (r >= M) continue;
#pragma unroll
        for (int j = 0; j < 8; j += 4) {
            int c = col0 + tx * 8 + j;
            float v[4];
#pragma unroll
            for (int q = 0; q < 4; q++) {
                float val = c_acc * acc[i][j + q];
                if (c_id != 0.f)
                    val += c_id * scale_a * __ldg(&A[(size_t)r * K + (c + q)]);
                if (bias) val += __ldg(&bias[c + q]);
                if (do_relu) val = fmaxf(val, 0.f);
                v[q] = val;
            }
            float4 ov = make_float4(v[0], v[1], v[2], v[3]);
            *(float4*)&C[(size_t)r * Nc + c] = ov;
            if (C2) *(float4*)&C2[(size_t)r * Nc + c] = ov;
        }
    }
}

// ---------------------------------------------------------------------------
// agg = s * src   (vectorized; n4 = number of float4)
// ---------------------------------------------------------------------------
__global__ void scale_copy_kernel(const float4* __restrict__ src,
                                  float4* __restrict__ dst, float s, int n4)
{
    int i = blockIdx.x * blockDim.x + threadIdx.x;
    if (i < n4) {
        float4 v = __ldg(&src[i]);
        v.x *= s; v.y *= s; v.z *= s; v.w *= s;
        dst[i] = v;
    }
}

// ---------------------------------------------------------------------------
// SpMM scatter: agg[row] += val * h[col]   one warp per edge, H=256 floats.
// Uses sm_90+ vector reduction red.global.add.v4.f32 (4x fewer L2 atomic ops).
// ---------------------------------------------------------------------------
__global__ __launch_bounds__(256)
void spmm_kernel(const int* __restrict__ erow, const int* __restrict__ ecol,
                 const float* __restrict__ eval, const float* __restrict__ h,
                 float* __restrict__ agg, int E)
{
    int warp = (blockIdx.x * blockDim.x + threadIdx.x) >> 5;
    int lane = threadIdx.x & 31;
    if (warp >= E) return;
    int r = __ldg(&erow[warp]);
    int c = __ldg(&ecol[warp]);
    float v = __ldg(&eval[warp]);
    const float4* src = (const float4*)(h + (size_t)c * HH);
    float* dst = agg + (size_t)r * HH;
#pragma unroll
    for (int it = 0; it < 2; it++) {
        int idx = lane + it * 32;                 // float4 index 0..63
        float4 f = __ldg(&src[idx]);
        f.x *= v; f.y *= v; f.z *= v; f.w *= v;
        asm volatile("red.global.add.v4.f32 [%0], {%1,%2,%3,%4};"
                     :: "l"(dst + (size_t)idx * 4),
                        "f"(f.x), "f"(f.y), "f"(f.z), "f"(f.w)
                     : "memory");
    }
}

// ---------------------------------------------------------------------------
// Output head: logits = h @ W_out + b_out, then log_softmax over 64 classes.
// One warp per row; each lane owns classes {lane, lane+32}.
// ---------------------------------------------------------------------------
__global__ __launch_bounds__(256)
void out_kernel(const float* __restrict__ h, const float* __restrict__ W,
                const float* __restrict__ b, float* __restrict__ out, int M)
{
    __shared__ float hs[8][HH];
    int tid = threadIdx.x;
    int warp = tid >> 5, lane = tid & 31;
    int row = blockIdx.x * 8 + warp;

    if (row < M) {
        const float4* hp = (const float4*)(h + (size_t)row * HH);
        float4* sp = (float4*)hs[warp];
        sp[lane] = __ldg(&hp[lane]);
        sp[lane + 32] = __ldg(&hp[lane + 32]);
    }
    __syncthreads();
    if (row >= M) return;

    float l0 = __ldg(&b[lane]);
    float l1 = __ldg(&b[lane + 32]);
#pragma unroll 8
    for (int k = 0; k < HH; k++) {
        float hv = hs[warp][k];
        l0 += hv * __ldg(&W[k * CC + lane]);
        l1 += hv * __ldg(&W[k * CC + lane + 32]);
    }
    float m = fmaxf(l0, l1);
#pragma unroll
    for (int o = 16; o; o >>= 1) m = fmaxf(m, __shfl_xor_sync(0xffffffffu, m, o));
    float s = expf(l0 - m) + expf(l1 - m);
#pragma unroll
    for (int o = 16; o; o >>= 1) s += __shfl_xor_sync(0xffffffffu, s, o);
    float lse = m + logf(s);
    out[(size_t)row * CC + lane] = l0 - lse;
    out[(size_t)row * CC + lane + 32] = l1 - lse;
}

// ---------------------------------------------------------------------------
extern "C" void kernel_launch(void* const* d_in, const int* in_sizes, int n_in,
                              void* d_out, int out_size)
{
    const float* x        = (const float*)d_in[0];
    const float* edge_val = (const float*)d_in[1];
    const float* W_in     = (const float*)d_in[2];
    const float* b_in     = (const float*)d_in[3];
    const float* conv_W   = (const float*)d_in[4];
    const float* W_out    = (const float*)d_in[5];
    const float* b_out    = (const float*)d_in[6];
    const int*   erow     = (const int*)d_in[7];
    const int*   ecol     = (const int*)d_in[8];
    float* out = (float*)d_out;

    float *h, *x0, *agg;
    cudaGetSymbolAddress((void**)&h,   g_h);
    cudaGetSymbolAddress((void**)&x0,  g_x0);
    cudaGetSymbolAddress((void**)&agg, g_agg);

    const float ALPHA = 0.1f;
    const int n4 = (NN * HH) / 4;          // 6.4M float4
    dim3 gemm_grid(HH / 128, (NN + 127) / 128);   // (2, 782)

    // h = relu(x @ W_in + b_in);  x0 = h
    sgemm_kernel<<<gemm_grid, 256>>>(x, W_in, b_in, h, x0,
                                     NN, FIN, HH, 1.f, 1.f, 0.f, 1);

    for (int l = 0; l < LL; l++) {
        float beta = logf(0.5f / (float)(l + 1) + 1.0f);
        // agg = (alpha/(1-alpha)) * x0   (init fold: mix = (1-alpha)*agg after spmm)
        scale_copy_kernel<<<(n4 + 255) / 256, 256>>>(
            (const float4*)x0, (float4*)agg, ALPHA / (1.f - ALPHA), n4);
        // agg += A @ h
        spmm_kernel<<<(EE + 7) / 8, 256>>>(erow, ecol, edge_val, h, agg, EE);
        // h = relu( (1-beta)*0.9*agg + beta * (0.9*agg @ conv_W[l]) )
        sgemm_kernel<<<gemm_grid, 256>>>(agg, conv_W + (size_t)l * HH * HH, nullptr,
                                         h, nullptr, NN, HH, HH,
                                         1.f - ALPHA, beta, 1.f - beta, 1);
    }

    // log_softmax(h @ W_out + b_out)
    out_kernel<<<(NN + 7) / 8, 256>>>(h, W_out, b_out, out, NN);
}

// round 4
// speedup vs baseline: 1.8117x; 1.8117x over previous
#include <cuda_runtime.h>
#include <math.h>

#define NN 100000
#define EE 3200000
#define FIN 512
#define HH 256
#define CC 64
#define LL 8
#define ALPHA 0.1f

// Scratch (no cudaMalloc allowed)
__device__ float g_h[(size_t)NN * HH];
__device__ float g_x0[(size_t)NN * HH];
__device__ float g_agg[(size_t)NN * HH];
__device__ int   g_rowptr[NN + 1];
__device__ int   g_cnt[NN];
__device__ int   g_col[EE];
__device__ float g_val[EE];

// ---------------------------------------------------------------------------
// SGEMM: C = epilogue( c_acc * (scale_a*A)@B + c_id * scale_a*A[i][j] + bias )
// ---------------------------------------------------------------------------
__global__ __launch_bounds__(256, 2)
void sgemm_kernel(const float* __restrict__ A, const float* __restrict__ B,
                  const float* __restrict__ bias,
                  float* __restrict__ C, float* __restrict__ C2,
                  int M, int K, int Nc,
                  float scale_a, float c_acc, float c_id, int do_relu)
{
    __shared__ float As[8][128];
    __shared__ float Bs[8][128];

    const int tid = threadIdx.x;
    const int row0 = blockIdx.y * 128;
    const int col0 = blockIdx.x * 128;
    const int tx = tid & 15;
    const int ty = tid >> 4;

    float acc[8][8];
#pragma unroll
    for (int i = 0; i < 8; i++)
#pragma unroll
        for (int j = 0; j < 8; j++) acc[i][j] = 0.f;

    const int a_row = tid >> 1;
    const int a_col4 = (tid & 1) * 4;
    const int b_row = tid >> 5;
    const int b_col4 = (tid & 31) * 4;

    const bool a_valid = (row0 + a_row) < M;
    const float* Aptr = A + (size_t)(row0 + a_row) * K + a_col4;
    const float* Bptr = B + (size_t)b_row * Nc + col0 + b_col4;

    for (int k0 = 0; k0 < K; k0 += 8) {
        float4 av = a_valid ? *(const float4*)Aptr : make_float4(0.f, 0.f, 0.f, 0.f);
        float4 bv = *(const float4*)Bptr;
        As[a_col4 + 0][a_row] = av.x * scale_a;
        As[a_col4 + 1][a_row] = av.y * scale_a;
        As[a_col4 + 2][a_row] = av.z * scale_a;
        As[a_col4 + 3][a_row] = av.w * scale_a;
        *(float4*)&Bs[b_row][b_col4] = bv;
        __syncthreads();

#pragma unroll
        for (int kk = 0; kk < 8; kk++) {
            float areg[8], breg[8];
#pragma unroll
            for (int i = 0; i < 8; i++) areg[i] = As[kk][ty * 8 + i];
#pragma unroll
            for (int j = 0; j < 8; j++) breg[j] = Bs[kk][tx * 8 + j];
#pragma unroll
            for (int i = 0; i < 8; i++)
#pragma unroll
                for (int j = 0; j < 8; j++)
                    acc[i][j] += areg[i] * breg[j];
        }
        __syncthreads();
        Aptr += 8;
        Bptr += (size_t)8 * Nc;
    }

#pragma unroll
    for (int i = 0; i < 8; i++) {
        int r = row0 + ty * 8 + i;
        if (r >= M) continue;
#pragma unroll
        for (int j = 0; j < 8; j += 4) {
            int c = col0 + tx * 8 + j;
            float v[4];
#pragma unroll
            for (int q = 0; q < 4; q++) {
                float val = c_acc * acc[i][j + q];
                if (c_id != 0.f)
                    val += c_id * scale_a * __ldg(&A[(size_t)r * K + (c + q)]);
                if (bias) val += __ldg(&bias[c + q]);
                if (do_relu) val = fmaxf(val, 0.f);
                v[q] = val;
            }
            float4 ov = make_float4(v[0], v[1], v[2], v[3]);
            *(float4*)&C[(size_t)r * Nc + c] = ov;
            if (C2) *(float4*)&C2[(size_t)r * Nc + c] = ov;
        }
    }
}

// ---------------------------------------------------------------------------
// CSR build: histogram -> scan -> scatter
// ---------------------------------------------------------------------------
__global__ void hist_kernel(const int* __restrict__ erow, int* __restrict__ cnt, int E)
{
    for (int e = blockIdx.x * blockDim.x + threadIdx.x; e < E;
         e += gridDim.x * blockDim.x)
        atomicAdd(&cnt[__ldg(&erow[e])], 1);
}

// single-block exclusive scan over NN counters -> rowptr
__global__ __launch_bounds__(1024)
void scan_kernel(const int* __restrict__ cnt, int* __restrict__ rowptr)
{
    __shared__ int warpsums[32];
    __shared__ int running;
    int tid = threadIdx.x, lane = tid & 31, wid = tid >> 5;
    if (tid == 0) running = 0;
    __syncthreads();
    for (int base = 0; base < NN; base += 1024) {
        int v = (base + tid < NN) ? cnt[base + tid] : 0;
        int x = v;
#pragma unroll
        for (int o = 1; o < 32; o <<= 1) {
            int t = __shfl_up_sync(0xffffffffu, x, o);
            if (lane >= o) x += t;
        }
        if (lane == 31) warpsums[wid] = x;
        __syncthreads();
        if (wid == 0) {
            int s = warpsums[lane];
#pragma unroll
            for (int o = 1; o < 32; o <<= 1) {
                int t = __shfl_up_sync(0xffffffffu, s, o);
                if (lane >= o) s += t;
            }
            warpsums[lane] = s;
        }
        __syncthreads();
        int incl = x + (wid > 0 ? warpsums[wid - 1] : 0) + running;
        if (base + tid < NN) rowptr[base + tid + 1] = incl;
        __syncthreads();
        if (tid == 1023) running = incl;
        __syncthreads();
    }
    if (tid == 0) rowptr[0] = 0;
}

__global__ void scatter_kernel(const int* __restrict__ erow,
                               const int* __restrict__ ecol,
                               const float* __restrict__ eval,
                               const int* __restrict__ rowptr,
                               int* __restrict__ cnt,
                               int* __restrict__ csr_col,
                               float* __restrict__ csr_val, int E)
{
    for (int e = blockIdx.x * blockDim.x + threadIdx.x; e < E;
         e += gridDim.x * blockDim.x) {
        int r = __ldg(&erow[e]);
        int p = __ldg(&rowptr[r]) + atomicAdd(&cnt[r], 1);
        csr_col[p] = __ldg(&ecol[e]);
        csr_val[p] = __ldg(&eval[e]) * (1.0f - ALPHA);  // fold (1-alpha)
    }
}

// ---------------------------------------------------------------------------
// CSR SpMM, fused residual: mix[r] = alpha*x0[r] + sum_{e in row r} val'*h[col]
// 64-thread group per row; each thread owns one float4 (4 channels).
// ---------------------------------------------------------------------------
__global__ __launch_bounds__(256)
void spmm_csr_kernel(const int* __restrict__ rowptr,
                     const int* __restrict__ cols,
                     const float* __restrict__ vals,
                     const float* __restrict__ h,
                     const float* __restrict__ x0,
                     float* __restrict__ mix, int M)
{
    int row = (blockIdx.x * 256 + threadIdx.x) >> 6;
    int t = threadIdx.x & 63;
    if (row >= M) return;

    int s = __ldg(&rowptr[row]);
    int e = __ldg(&rowptr[row + 1]);

    float4 acc = __ldg((const float4*)(x0 + (size_t)row * HH) + t);
    acc.x *= ALPHA; acc.y *= ALPHA; acc.z *= ALPHA; acc.w *= ALPHA;

    int i = s;
    for (; i + 4 <= e; i += 4) {
        int   c0 = __ldg(&cols[i]),     c1 = __ldg(&cols[i + 1]);
        int   c2 = __ldg(&cols[i + 2]), c3 = __ldg(&cols[i + 3]);
        float v0 = __ldg(&vals[i]),     v1 = __ldg(&vals[i + 1]);
        float v2 = __ldg(&vals[i + 2]), v3 = __ldg(&vals[i + 3]);
        float4 f0 = __ldg((const float4*)(h + (size_t)c0 * HH) + t);
        float4 f1 = __ldg((const float4*)(h + (size_t)c1 * HH) + t);
        float4 f2 = __ldg((const float4*)(h + (size_t)c2 * HH) + t);
        float4 f3 = __ldg((const float4*)(h + (size_t)c3 * HH) + t);
        acc.x += v0 * f0.x + v1 * f1.x + v2 * f2.x + v3 * f3.x;
        acc.y += v0 * f0.y + v1 * f1.y + v2 * f2.y + v3 * f3.y;
        acc.z += v0 * f0.z + v1 * f1.z + v2 * f2.z + v3 * f3.z;
        acc.w += v0 * f0.w + v1 * f1.w + v2 * f2.w + v3 * f3.w;
    }
    for (; i < e; i++) {
        int c = __ldg(&cols[i]);
        float v = __ldg(&vals[i]);
        float4 f = __ldg((const float4*)(h + (size_t)c * HH) + t);
        acc.x += v * f.x; acc.y += v * f.y; acc.z += v * f.z; acc.w += v * f.w;
    }
    ((float4*)(mix + (size_t)row * HH))[t] = acc;
}

// ---------------------------------------------------------------------------
// Output head: log_softmax(h @ W_out + b_out)
// ---------------------------------------------------------------------------
__global__ __launch_bounds__(256)
void out_kernel(const float* __restrict__ h, const float* __restrict__ W,
                const float* __restrict__ b, float* __restrict__ out, int M)
{
    __shared__ float hs[8][HH];
    int tid = threadIdx.x;
    int warp = tid >> 5, lane = tid & 31;
    int row = blockIdx.x * 8 + warp;

    if (row < M) {
        const float4* hp = (const float4*)(h + (size_t)row * HH);
        float4* sp = (float4*)hs[warp];
        sp[lane] = __ldg(&hp[lane]);
        sp[lane + 32] = __ldg(&hp[lane + 32]);
    }
    __syncthreads();
    if (row >= M) return;

    float l0 = __ldg(&b[lane]);
    float l1 = __ldg(&b[lane + 32]);
#pragma unroll 8
    for (int k = 0; k < HH; k++) {
        float hv = hs[warp][k];
        l0 += hv * __ldg(&W[k * CC + lane]);
        l1 += hv * __ldg(&W[k * CC + lane + 32]);
    }
    float m = fmaxf(l0, l1);
#pragma unroll
    for (int o = 16; o; o >>= 1) m = fmaxf(m, __shfl_xor_sync(0xffffffffu, m, o));
    float s = expf(l0 - m) + expf(l1 - m);
#pragma unroll
    for (int o = 16; o; o >>= 1) s += __shfl_xor_sync(0xffffffffu, s, o);
    float lse = m + logf(s);
    out[(size_t)row * CC + lane] = l0 - lse;
    out[(size_t)row * CC + lane + 32] = l1 - lse;
}

// ---------------------------------------------------------------------------
extern "C" void kernel_launch(void* const* d_in, const int* in_sizes, int n_in,
                              void* d_out, int out_size)
{
    const float* x        = (const float*)d_in[0];
    const float* edge_val = (const float*)d_in[1];
    const float* W_in     = (const float*)d_in[2];
    const float* b_in     = (const float*)d_in[3];
    const float* conv_W   = (const float*)d_in[4];
    const float* W_out    = (const float*)d_in[5];
    const float* b_out    = (const float*)d_in[6];
    const int*   erow     = (const int*)d_in[7];
    const int*   ecol     = (const int*)d_in[8];
    float* out = (float*)d_out;

    float *h, *x0, *agg, *csr_val;
    int *rowptr, *cnt, *csr_col;
    cudaGetSymbolAddress((void**)&h,       g_h);
    cudaGetSymbolAddress((void**)&x0,      g_x0);
    cudaGetSymbolAddress((void**)&agg,     g_agg);
    cudaGetSymbolAddress((void**)&rowptr,  g_rowptr);
    cudaGetSymbolAddress((void**)&cnt,     g_cnt);
    cudaGetSymbolAddress((void**)&csr_col, g_col);
    cudaGetSymbolAddress((void**)&csr_val, g_val);

    dim3 gemm_grid(HH / 128, (NN + 127) / 128);

    // ---- CSR build (in-graph, per replay) ----
    cudaMemsetAsync(cnt, 0, NN * sizeof(int));
    hist_kernel<<<592, 256>>>(erow, cnt, EE);
    scan_kernel<<<1, 1024>>>(cnt, rowptr);
    cudaMemsetAsync(cnt, 0, NN * sizeof(int));
    scatter_kernel<<<592, 256>>>(erow, ecol, edge_val, rowptr, cnt,
                                 csr_col, csr_val, EE);

    // ---- h = relu(x @ W_in + b_in); x0 = h ----
    sgemm_kernel<<<gemm_grid, 256>>>(x, W_in, b_in, h, x0,
                                     NN, FIN, HH, 1.f, 1.f, 0.f, 1);

    for (int l = 0; l < LL; l++) {
        float beta = logf(0.5f / (float)(l + 1) + 1.0f);
        // agg = mix = alpha*x0 + (1-alpha) * A @ h   (CSR, register accum)
        spmm_csr_kernel<<<(NN + 3) / 4, 256>>>(rowptr, csr_col, csr_val,
                                               h, x0, agg, NN);
        // h = relu( (1-beta)*mix + beta*(mix @ conv_W[l]) )
        sgemm_kernel<<<gemm_grid, 256>>>(agg, conv_W + (size_t)l * HH * HH,
                                         nullptr, h, nullptr, NN, HH, HH,
                                         1.f, beta, 1.f - beta, 1);
    }

    out_kernel<<<(NN + 7) / 8, 256>>>(h, W_out, b_out, out, NN);
}

// round 6
// speedup vs baseline: 2.9740x; 1.6416x over previous
#include <cuda_runtime.h>
#include <cuda_bf16.h>
#include <math.h>
#include <stdint.h>

#define NN 100000
#define EE 3200000
#define FIN 512
#define HH 256
#define CC 64
#define LL 8
#define ALPHA 0.1f

// B chunk library: 8 input chunks (K=512) + 8 layers * 4 chunks (K=256)
// Each chunk: 256 n-rows x 64 k-cols, plain row-major [n][k] bf16.
#define NCHUNKS_TOT 40
#define CHUNK_ELEMS 16384

// ---------------- scratch (no cudaMalloc allowed) ----------------
__device__ float g_h[(size_t)NN * HH];
__device__ float g_x0[(size_t)NN * HH];
__device__ float g_agg[(size_t)NN * HH];
__device__ int   g_rowptr[NN + 1];
__device__ int   g_cnt[NN];
__device__ int   g_col[EE];
__device__ float g_val[EE];
__device__ __align__(16) uint16_t g_Bh[(size_t)NCHUNKS_TOT * CHUNK_ELEMS];
__device__ __align__(16) uint16_t g_Bl[(size_t)NCHUNKS_TOT * CHUNK_ELEMS];

// ---------------------------------------------------------------------------
// bf16 hi/lo split helpers
// ---------------------------------------------------------------------------
__device__ __forceinline__ uint16_t bf16_bits(float v) {
    __nv_bfloat16 b = __float2bfloat16_rn(v);
    return *reinterpret_cast<uint16_t*>(&b);
}
__device__ __forceinline__ float bf16_val(uint16_t u) {
    __nv_bfloat16 b = *reinterpret_cast<__nv_bfloat16*>(&u);
    return __bfloat162float(b);
}

__device__ __forceinline__ void mma16816(float* d, const uint32_t* a,
                                         uint32_t b0, uint32_t b1) {
    asm volatile(
        "mma.sync.aligned.m16n8k16.row.col.f32.bf16.bf16.f32 "
        "{%0,%1,%2,%3}, {%4,%5,%6,%7}, {%8,%9}, {%0,%1,%2,%3};"
        : "+f"(d[0]), "+f"(d[1]), "+f"(d[2]), "+f"(d[3])
        : "r"(a[0]), "r"(a[1]), "r"(a[2]), "r"(a[3]), "r"(b0), "r"(b1));
}

// ---------------------------------------------------------------------------
// Precompute B chunk library (bf16 hi/lo, [chunk][n][k] row-major).
// Chunks 0..7: W_in (K=512). Chunk 8+4l+c: W'[l] = beta*conv_W[l] + (1-beta)*I.
// ---------------------------------------------------------------------------
__global__ void prep_B_kernel(const float* __restrict__ Win,
                              const float* __restrict__ convW,
                              uint16_t* __restrict__ Bh, uint16_t* __restrict__ Bl)
{
    int e = blockIdx.x * 256 + threadIdx.x;
    if (e >= NCHUNKS_TOT * CHUNK_ELEMS) return;
    int chunk = e >> 14, w = e & 16383;
    int n = w >> 6, kk = w & 63;
    float val;
    if (chunk < 8) {
        val = __ldg(&Win[(chunk * 64 + kk) * HH + n]);
    } else {
        int l = (chunk - 8) >> 2, c = (chunk - 8) & 3, k = c * 64 + kk;
        float beta = logf(0.5f / (float)(l + 1) + 1.0f);
        val = beta * __ldg(&convW[(size_t)l * HH * HH + (size_t)k * HH + n]);
        if (k == n) val += 1.0f - beta;
    }
    uint16_t hi = bf16_bits(val);
    uint16_t lo = bf16_bits(val - bf16_val(hi));
    Bh[e] = hi;
    Bl[e] = lo;
}

// ---------------------------------------------------------------------------
// HMMA GEMM: C = relu( A[MxK] @ Bchunks + bias ), bf16 3-term split.
// BM=128, BN=128, BK=64, 256 threads (8 warps: 4 in M x 2 in N).
// Warp tile 32x64 -> 2 m-tiles x 8 n-tiles of m16n8, 64 accums/thread.
// Smem rows padded to 72 bf16 -> conflict-free 32-bit fragment loads.
// ---------------------------------------------------------------------------
#define LDP 72
#define SA_ELEMS (128 * LDP)
__global__ __launch_bounds__(256, 2)
void mma_gemm(const float* __restrict__ A,
              const uint16_t* __restrict__ Bh, const uint16_t* __restrict__ Bl,
              int chunk0, int nchunks, int K,
              const float* __restrict__ bias,
              float* __restrict__ C, float* __restrict__ C2, int M)
{
    extern __shared__ uint16_t sm[];
    uint16_t* sAh = sm;
    uint16_t* sAl = sm + SA_ELEMS;
    uint16_t* sBh = sm + 2 * SA_ELEMS;
    uint16_t* sBl = sm + 3 * SA_ELEMS;

    const int tid = threadIdx.x;
    const int warp = tid >> 5, lane = tid & 31;
    const int wm = warp >> 1, wn = warp & 1;      // 4 x 2 warp grid
    const int g = lane >> 2, t = lane & 3;
    const int row0 = blockIdx.y * 128;
    const int col0 = blockIdx.x * 128;

    float acc[2][8][4];
#pragma unroll
    for (int mi = 0; mi < 2; mi++)
#pragma unroll
        for (int ni = 0; ni < 8; ni++)
#pragma unroll
            for (int q = 0; q < 4; q++) acc[mi][ni][q] = 0.f;

    for (int c = 0; c < nchunks; c++) {
        __syncthreads();
        // ---- stage A chunk: 128 rows x 64 k, fp32 -> bf16 hi/lo ----
#pragma unroll
        for (int i = 0; i < 8; i++) {
            int f = tid + i * 256;          // float4 index, 16 per row
            int r = f >> 4, kq = (f & 15) * 4;
            float4 v = make_float4(0.f, 0.f, 0.f, 0.f);
            if (row0 + r < M)
                v = *(const float4*)(A + (size_t)(row0 + r) * K + c * 64 + kq);
            uint16_t h0 = bf16_bits(v.x), h1 = bf16_bits(v.y);
            uint16_t h2 = bf16_bits(v.z), h3 = bf16_bits(v.w);
            uint16_t l0 = bf16_bits(v.x - bf16_val(h0));
            uint16_t l1 = bf16_bits(v.y - bf16_val(h1));
            uint16_t l2 = bf16_bits(v.z - bf16_val(h2));
            uint16_t l3 = bf16_bits(v.w - bf16_val(h3));
            int base = r * LDP + kq;
            *(uint32_t*)&sAh[base]     = (uint32_t)h0 | ((uint32_t)h1 << 16);
            *(uint32_t*)&sAh[base + 2] = (uint32_t)h2 | ((uint32_t)h3 << 16);
            *(uint32_t*)&sAl[base]     = (uint32_t)l0 | ((uint32_t)l1 << 16);
            *(uint32_t*)&sAl[base + 2] = (uint32_t)l2 | ((uint32_t)l3 << 16);
        }
        // ---- stage B chunk: 128 n-rows x 64 k (pre-split library) ----
        {
            const size_t cb = ((size_t)(chunk0 + c) << 14) + (size_t)col0 * 64;
#pragma unroll
            for (int i = 0; i < 4; i++) {
                int f = tid + i * 256;      // uint4 index, 8 per n-row
                int n = f >> 3, k8 = (f & 7) * 8;
                uint4 vh = *(const uint4*)(Bh + cb + n * 64 + k8);
                uint4 vl = *(const uint4*)(Bl + cb + n * 64 + k8);
                *(uint4*)&sBh[n * LDP + k8] = vh;
                *(uint4*)&sBl[n * LDP + k8] = vl;
            }
        }
        __syncthreads();

        // ---- compute: 4 k-steps of 16 ----
#pragma unroll
        for (int ks = 0; ks < 4; ks++) {
            uint32_t ah[2][4], al[2][4];
#pragma unroll
            for (int mi = 0; mi < 2; mi++) {
                int base = (wm * 32 + mi * 16 + g) * LDP + ks * 16 + 2 * t;
                ah[mi][0] = *(const uint32_t*)&sAh[base];
                ah[mi][1] = *(const uint32_t*)&sAh[base + 8 * LDP];
                ah[mi][2] = *(const uint32_t*)&sAh[base + 8];
                ah[mi][3] = *(const uint32_t*)&sAh[base + 8 * LDP + 8];
                al[mi][0] = *(const uint32_t*)&sAl[base];
                al[mi][1] = *(const uint32_t*)&sAl[base + 8 * LDP];
                al[mi][2] = *(const uint32_t*)&sAl[base + 8];
                al[mi][3] = *(const uint32_t*)&sAl[base + 8 * LDP + 8];
            }
#pragma unroll
            for (int ni = 0; ni < 8; ni++) {
                int bb = (wn * 64 + ni * 8 + g) * LDP + ks * 16 + 2 * t;
                uint32_t bh0 = *(const uint32_t*)&sBh[bb];
                uint32_t bh1 = *(const uint32_t*)&sBh[bb + 8];
                uint32_t bl0 = *(const uint32_t*)&sBl[bb];
                uint32_t bl1 = *(const uint32_t*)&sBl[bb + 8];
#pragma unroll
                for (int mi = 0; mi < 2; mi++) {
                    mma16816(acc[mi][ni], ah[mi], bh0, bh1);
                    mma16816(acc[mi][ni], ah[mi], bl0, bl1);
                    mma16816(acc[mi][ni], al[mi], bh0, bh1);
                }
            }
        }
    }

    // ---- epilogue: bias + relu, write C (and optional C2) ----
#pragma unroll
    for (int mi = 0; mi < 2; mi++) {
        int r0 = row0 + wm * 32 + mi * 16 + g;
#pragma unroll
        for (int half = 0; half < 2; half++) {
            int r = r0 + half * 8;
            if (r >= M) continue;
#pragma unroll
            for (int ni = 0; ni < 8; ni++) {
                int cg = col0 + wn * 64 + ni * 8 + 2 * t;
                float v0 = acc[mi][ni][half * 2 + 0];
                float v1 = acc[mi][ni][half * 2 + 1];
                if (bias) { v0 += __ldg(&bias[cg]); v1 += __ldg(&bias[cg + 1]); }
                float2 o = make_float2(fmaxf(v0, 0.f), fmaxf(v1, 0.f));
                *(float2*)(C + (size_t)r * HH + cg) = o;
                if (C2) *(float2*)(C2 + (size_t)r * HH + cg) = o;
            }
        }
    }
}

// ---------------------------------------------------------------------------
// CSR build (unchanged)
// ---------------------------------------------------------------------------
__global__ void hist_kernel(const int* __restrict__ erow, int* __restrict__ cnt, int E)
{
    for (int e = blockIdx.x * blockDim.x + threadIdx.x; e < E;
         e += gridDim.x * blockDim.x)
        atomicAdd(&cnt[__ldg(&erow[e])], 1);
}

__global__ __launch_bounds__(1024)
void scan_kernel(const int* __restrict__ cnt, int* __restrict__ rowptr)
{
    __shared__ int warpsums[32];
    __shared__ int running;
    int tid = threadIdx.x, lane = tid & 31, wid = tid >> 5;
    if (tid == 0) running = 0;
    __syncthreads();
    for (int base = 0; base < NN; base += 1024) {
        int v = (base + tid < NN) ? cnt[base + tid] : 0;
        int x = v;
#pragma unroll
        for (int o = 1; o < 32; o <<= 1) {
            int t = __shfl_up_sync(0xffffffffu, x, o);
            if (lane >= o) x += t;
        }
        if (lane == 31) warpsums[wid] = x;
        __syncthreads();
        if (wid == 0) {
            int s = warpsums[lane];
#pragma unroll
            for (int o = 1; o < 32; o <<= 1) {
                int t = __shfl_up_sync(0xffffffffu, s, o);
                if (lane >= o) s += t;
            }
            warpsums[lane] = s;
        }
        __syncthreads();
        int incl = x + (wid > 0 ? warpsums[wid - 1] : 0) + running;
        if (base + tid < NN) rowptr[base + tid + 1] = incl;
        __syncthreads();
        if (tid == 1023) running = incl;
        __syncthreads();
    }
    if (tid == 0) rowptr[0] = 0;
}

__global__ void scatter_kernel(const int* __restrict__ erow,
                               const int* __restrict__ ecol,
                               const float* __restrict__ eval,
                               const int* __restrict__ rowptr,
                               int* __restrict__ cnt,
                               int* __restrict__ csr_col,
                               float* __restrict__ csr_val, int E)
{
    for (int e = blockIdx.x * blockDim.x + threadIdx.x; e < E;
         e += gridDim.x * blockDim.x) {
        int r = __ldg(&erow[e]);
        int p = __ldg(&rowptr[r]) + atomicAdd(&cnt[r], 1);
        csr_col[p] = __ldg(&ecol[e]);
        csr_val[p] = __ldg(&eval[e]) * (1.0f - ALPHA);
    }
}

// ---------------------------------------------------------------------------
// CSR SpMM fused residual (unchanged)
// ---------------------------------------------------------------------------
__global__ __launch_bounds__(256)
void spmm_csr_kernel(const int* __restrict__ rowptr,
                     const int* __restrict__ cols,
                     const float* __restrict__ vals,
                     const float* __restrict__ h,
                     const float* __restrict__ x0,
                     float* __restrict__ mix, int M)
{
    int row = (blockIdx.x * 256 + threadIdx.x) >> 6;
    int t = threadIdx.x & 63;
    if (row >= M) return;

    int s = __ldg(&rowptr[row]);
    int e = __ldg(&rowptr[row + 1]);

    float4 acc = __ldg((const float4*)(x0 + (size_t)row * HH) + t);
    acc.x *= ALPHA; acc.y *= ALPHA; acc.z *= ALPHA; acc.w *= ALPHA;

    int i = s;
    for (; i + 4 <= e; i += 4) {
        int   c0 = __ldg(&cols[i]),     c1 = __ldg(&cols[i + 1]);
        int   c2 = __ldg(&cols[i + 2]), c3 = __ldg(&cols[i + 3]);
        float v0 = __ldg(&vals[i]),     v1 = __ldg(&vals[i + 1]);
        float v2 = __ldg(&vals[i + 2]), v3 = __ldg(&vals[i + 3]);
        float4 f0 = __ldg((const float4*)(h + (size_t)c0 * HH) + t);
        float4 f1 = __ldg((const float4*)(h + (size_t)c1 * HH) + t);
        float4 f2 = __ldg((const float4*)(h + (size_t)c2 * HH) + t);
        float4 f3 = __ldg((const float4*)(h + (size_t)c3 * HH) + t);
        acc.x += v0 * f0.x + v1 * f1.x + v2 * f2.x + v3 * f3.x;
        acc.y += v0 * f0.y + v1 * f1.y + v2 * f2.y + v3 * f3.y;
        acc.z += v0 * f0.z + v1 * f1.z + v2 * f2.z + v3 * f3.z;
        acc.w += v0 * f0.w + v1 * f1.w + v2 * f2.w + v3 * f3.w;
    }
    for (; i < e; i++) {
        int c = __ldg(&cols[i]);
        float v = __ldg(&vals[i]);
        float4 f = __ldg((const float4*)(h + (size_t)c * HH) + t);
        acc.x += v * f.x; acc.y += v * f.y; acc.z += v * f.z; acc.w += v * f.w;
    }
    ((float4*)(mix + (size_t)row * HH))[t] = acc;
}

// ---------------------------------------------------------------------------
// Output head (unchanged)
// ---------------------------------------------------------------------------
__global__ __launch_bounds__(256)
void out_kernel(const float* __restrict__ h, const float* __restrict__ W,
                const float* __restrict__ b, float* __restrict__ out, int M)
{
    __shared__ float hs[8][HH];
    int tid = threadIdx.x;
    int warp = tid >> 5, lane = tid & 31;
    int row = blockIdx.x * 8 + warp;

    if (row < M) {
        const float4* hp = (const float4*)(h + (size_t)row * HH);
        float4* sp = (float4*)hs[warp];
        sp[lane] = __ldg(&hp[lane]);
        sp[lane + 32] = __ldg(&hp[lane + 32]);
    }
    __syncthreads();
    if (row >= M) return;

    float l0 = __ldg(&b[lane]);
    float l1 = __ldg(&b[lane + 32]);
#pragma unroll 8
    for (int k = 0; k < HH; k++) {
        float hv = hs[warp][k];
        l0 += hv * __ldg(&W[k * CC + lane]);
        l1 += hv * __ldg(&W[k * CC + lane + 32]);
    }
    float m = fmaxf(l0, l1);
#pragma unroll
    for (int o = 16; o; o >>= 1) m = fmaxf(m, __shfl_xor_sync(0xffffffffu, m, o));
    float s = expf(l0 - m) + expf(l1 - m);
#pragma unroll
    for (int o = 16; o; o >>= 1) s += __shfl_xor_sync(0xffffffffu, s, o);
    float lse = m + logf(s);
    out[(size_t)row * CC + lane] = l0 - lse;
    out[(size_t)row * CC + lane + 32] = l1 - lse;
}

// ---------------------------------------------------------------------------
extern "C" void kernel_launch(void* const* d_in, const int* in_sizes, int n_in,
                              void* d_out, int out_size)
{
    const float* x        = (const float*)d_in[0];
    const float* edge_val = (const float*)d_in[1];
    const float* W_in     = (const float*)d_in[2];
    const float* b_in     = (const float*)d_in[3];
    const float* conv_W   = (const float*)d_in[4];
    const float* W_out    = (const float*)d_in[5];
    const float* b_out    = (const float*)d_in[6];
    const int*   erow     = (const int*)d_in[7];
    const int*   ecol     = (const int*)d_in[8];
    float* out = (float*)d_out;

    float *h, *x0, *agg, *csr_val;
    int *rowptr, *cnt, *csr_col;
    uint16_t *Bh, *Bl;
    cudaGetSymbolAddress((void**)&h,       g_h);
    cudaGetSymbolAddress((void**)&x0,      g_x0);
    cudaGetSymbolAddress((void**)&agg,     g_agg);
    cudaGetSymbolAddress((void**)&rowptr,  g_rowptr);
    cudaGetSymbolAddress((void**)&cnt,     g_cnt);
    cudaGetSymbolAddress((void**)&csr_col, g_col);
    cudaGetSymbolAddress((void**)&csr_val, g_val);
    cudaGetSymbolAddress((void**)&Bh,      g_Bh);
    cudaGetSymbolAddress((void**)&Bl,      g_Bl);

    const int smem_bytes = 4 * SA_ELEMS * sizeof(uint16_t);   // 73728
    cudaFuncSetAttribute(mma_gemm,
                         cudaFuncAttributeMaxDynamicSharedMemorySize, smem_bytes);

    dim3 gemm_grid(2, (NN + 127) / 128);   // (2, 782)

    // ---- B library precompute + CSR build (per replay, deterministic) ----
    prep_B_kernel<<<(NCHUNKS_TOT * CHUNK_ELEMS + 255) / 256, 256>>>(
        W_in, conv_W, Bh, Bl);
    cudaMemsetAsync(cnt, 0, NN * sizeof(int));
    hist_kernel<<<592, 256>>>(erow, cnt, EE);
    scan_kernel<<<1, 1024>>>(cnt, rowptr);
    cudaMemsetAsync(cnt, 0, NN * sizeof(int));
    scatter_kernel<<<592, 256>>>(erow, ecol, edge_val, rowptr, cnt,
                                 csr_col, csr_val, EE);

    // ---- h = relu(x @ W_in + b_in); x0 = h ----
    mma_gemm<<<gemm_grid, 256, smem_bytes>>>(x, Bh, Bl, 0, 8, FIN,
                                             b_in, h, x0, NN);

    for (int l = 0; l < LL; l++) {
        // mix = alpha*x0 + (1-alpha) * A @ h
        spmm_csr_kernel<<<(NN + 3) / 4, 256>>>(rowptr, csr_col, csr_val,
                                               h, x0, agg, NN);
        // h = relu( mix @ ((1-beta)I + beta*W_l) )
        mma_gemm<<<gemm_grid, 256, smem_bytes>>>(agg, Bh, Bl, 8 + 4 * l, 4, HH,
                                                 nullptr, h, nullptr, NN);
    }

    out_kernel<<<(NN + 7) / 8, 256>>>(h, W_out, b_out, out, NN);
}

// round 11
// speedup vs baseline: 4.0541x; 1.3632x over previous
#include <cuda_runtime.h>
#include <cuda_bf16.h>
#include <cuda_fp16.h>
#include <math.h>
#include <stdint.h>

#define NN 100000
#define EE 3200000
#define FIN 512
#define HH 256
#define CC 64
#define LL 8
#define ALPHA 0.1f
#define SCL 0.0625f                     // per-layer storage scale s = 1/16
#define UNSCALE 4294967296.0f           // s^-8 = 16^8 = 2^32 (exact fp32)

// B chunk library: 8 input chunks (K=512) + 8 layers * 4 chunks (K=256)
#define NCHUNKS_TOT 40
#define CHUNK_ELEMS 16384

// ---------------- scratch (no cudaMalloc allowed) ----------------
__device__ __align__(16) __half g_hh[(size_t)NN * HH];  // scaled h, fp16
__device__ float  g_x0[(size_t)NN * HH];
__device__ float  g_agg[(size_t)NN * HH];               // scaled mix, fp32
__device__ int    g_rowptr[NN + 1];
__device__ int    g_cnt[NN];
__device__ int    g_col[EE];
__device__ float  g_val[EE];
__device__ __align__(16) uint16_t g_Bh[(size_t)NCHUNKS_TOT * CHUNK_ELEMS];
__device__ __align__(16) uint16_t g_Bl[(size_t)NCHUNKS_TOT * CHUNK_ELEMS];

// ---------------------------------------------------------------------------
__device__ __forceinline__ uint16_t bf16_bits(float v) {
    __nv_bfloat16 b = __float2bfloat16_rn(v);
    return *reinterpret_cast<uint16_t*>(&b);
}
__device__ __forceinline__ float bf16_val(uint16_t u) {
    __nv_bfloat16 b = *reinterpret_cast<__nv_bfloat16*>(&u);
    return __bfloat162float(b);
}

__device__ __forceinline__ void mma16816(float* d, const uint32_t* a,
                                         uint32_t b0, uint32_t b1) {
    asm volatile(
        "mma.sync.aligned.m16n8k16.row.col.f32.bf16.bf16.f32 "
        "{%0,%1,%2,%3}, {%4,%5,%6,%7}, {%8,%9}, {%0,%1,%2,%3};"
        : "+f"(d[0]), "+f"(d[1]), "+f"(d[2]), "+f"(d[3])
        : "r"(a[0]), "r"(a[1]), "r"(a[2]), "r"(a[3]), "r"(b0), "r"(b1));
}

// ---------------------------------------------------------------------------
// B chunk library
// ---------------------------------------------------------------------------
__global__ void prep_B_kernel(const float* __restrict__ Win,
                              const float* __restrict__ convW,
                              uint16_t* __restrict__ Bh, uint16_t* __restrict__ Bl)
{
    int e = blockIdx.x * 256 + threadIdx.x;
    if (e >= NCHUNKS_TOT * CHUNK_ELEMS) return;
    int chunk = e >> 14, w = e & 16383;
    int n = w >> 6, kk = w & 63;
    float val;
    if (chunk < 8) {
        val = __ldg(&Win[(chunk * 64 + kk) * HH + n]);
    } else {
        int l = (chunk - 8) >> 2, c = (chunk - 8) & 3, k = c * 64 + kk;
        float beta = logf(0.5f / (float)(l + 1) + 1.0f);
        val = beta * __ldg(&convW[(size_t)l * HH * HH + (size_t)k * HH + n]);
        if (k == n) val += 1.0f - beta;
    }
    uint16_t hi = bf16_bits(val);
    uint16_t lo = bf16_bits(val - bf16_val(hi));
    Bh[e] = hi;
    Bl[e] = lo;
}

// ---------------------------------------------------------------------------
// HMMA GEMM: Ch(half) = relu( A @ Bchunks + bias );  Cf(fp32) optional dual.
// ---------------------------------------------------------------------------
#define LDP 72
#define SA_ELEMS (128 * LDP)
__global__ __launch_bounds__(256, 2)
void mma_gemm(const float* __restrict__ A,
              const uint16_t* __restrict__ Bh, const uint16_t* __restrict__ Bl,
              int chunk0, int nchunks, int K,
              const float* __restrict__ bias,
              __half* __restrict__ Ch, float* __restrict__ Cf, int M)
{
    extern __shared__ uint16_t sm[];
    uint16_t* sAh = sm;
    uint16_t* sAl = sm + SA_ELEMS;
    uint16_t* sBh = sm + 2 * SA_ELEMS;
    uint16_t* sBl = sm + 3 * SA_ELEMS;

    const int tid = threadIdx.x;
    const int warp = tid >> 5, lane = tid & 31;
    const int wm = warp >> 1, wn = warp & 1;
    const int g = lane >> 2, t = lane & 3;
    const int row0 = blockIdx.y * 128;
    const int col0 = blockIdx.x * 128;

    float acc[2][8][4];
#pragma unroll
    for (int mi = 0; mi < 2; mi++)
#pragma unroll
        for (int ni = 0; ni < 8; ni++)
#pragma unroll
            for (int q = 0; q < 4; q++) acc[mi][ni][q] = 0.f;

    for (int c = 0; c < nchunks; c++) {
        __syncthreads();
#pragma unroll
        for (int i = 0; i < 8; i++) {
            int f = tid + i * 256;
            int r = f >> 4, kq = (f & 15) * 4;
            float4 v = make_float4(0.f, 0.f, 0.f, 0.f);
            if (row0 + r < M)
                v = *(const float4*)(A + (size_t)(row0 + r) * K + c * 64 + kq);
            uint16_t h0 = bf16_bits(v.x), h1 = bf16_bits(v.y);
            uint16_t h2 = bf16_bits(v.z), h3 = bf16_bits(v.w);
            uint16_t l0 = bf16_bits(v.x - bf16_val(h0));
            uint16_t l1 = bf16_bits(v.y - bf16_val(h1));
            uint16_t l2 = bf16_bits(v.z - bf16_val(h2));
            uint16_t l3 = bf16_bits(v.w - bf16_val(h3));
            int base = r * LDP + kq;
            *(uint32_t*)&sAh[base]     = (uint32_t)h0 | ((uint32_t)h1 << 16);
            *(uint32_t*)&sAh[base + 2] = (uint32_t)h2 | ((uint32_t)h3 << 16);
            *(uint32_t*)&sAl[base]     = (uint32_t)l0 | ((uint32_t)l1 << 16);
            *(uint32_t*)&sAl[base + 2] = (uint32_t)l2 | ((uint32_t)l3 << 16);
        }
        {
            const size_t cb = ((size_t)(chunk0 + c) << 14) + (size_t)col0 * 64;
#pragma unroll
            for (int i = 0; i < 4; i++) {
                int f = tid + i * 256;
                int n = f >> 3, k8 = (f & 7) * 8;
                uint4 vh = *(const uint4*)(Bh + cb + n * 64 + k8);
                uint4 vl = *(const uint4*)(Bl + cb + n * 64 + k8);
                *(uint4*)&sBh[n * LDP + k8] = vh;
                *(uint4*)&sBl[n * LDP + k8] = vl;
            }
        }
        __syncthreads();

#pragma unroll
        for (int ks = 0; ks < 4; ks++) {
            uint32_t ah[2][4], al[2][4];
#pragma unroll
            for (int mi = 0; mi < 2; mi++) {
                int base = (wm * 32 + mi * 16 + g) * LDP + ks * 16 + 2 * t;
                ah[mi][0] = *(const uint32_t*)&sAh[base];
                ah[mi][1] = *(const uint32_t*)&sAh[base + 8 * LDP];
                ah[mi][2] = *(const uint32_t*)&sAh[base + 8];
                ah[mi][3] = *(const uint32_t*)&sAh[base + 8 * LDP + 8];
                al[mi][0] = *(const uint32_t*)&sAl[base];
                al[mi][1] = *(const uint32_t*)&sAl[base + 8 * LDP];
                al[mi][2] = *(const uint32_t*)&sAl[base + 8];
                al[mi][3] = *(const uint32_t*)&sAl[base + 8 * LDP + 8];
            }
#pragma unroll
            for (int ni = 0; ni < 8; ni++) {
                int bb = (wn * 64 + ni * 8 + g) * LDP + ks * 16 + 2 * t;
                uint32_t bh0 = *(const uint32_t*)&sBh[bb];
                uint32_t bh1 = *(const uint32_t*)&sBh[bb + 8];
                uint32_t bl0 = *(const uint32_t*)&sBl[bb];
                uint32_t bl1 = *(const uint32_t*)&sBl[bb + 8];
#pragma unroll
                for (int mi = 0; mi < 2; mi++) {
                    mma16816(acc[mi][ni], ah[mi], bh0, bh1);
                    mma16816(acc[mi][ni], ah[mi], bl0, bl1);
                    mma16816(acc[mi][ni], al[mi], bh0, bh1);
                }
            }
        }
    }

    // Epilogue: bias + relu -> half (clamped), fp32 (optional, exact)
#pragma unroll
    for (int mi = 0; mi < 2; mi++) {
        int r0 = row0 + wm * 32 + mi * 16 + g;
#pragma unroll
        for (int half_ = 0; half_ < 2; half_++) {
            int r = r0 + half_ * 8;
            if (r >= M) continue;
#pragma unroll
            for (int ni = 0; ni < 8; ni++) {
                int cg = col0 + wn * 64 + ni * 8 + 2 * t;
                float v0 = acc[mi][ni][half_ * 2 + 0];
                float v1 = acc[mi][ni][half_ * 2 + 1];
                if (bias) { v0 += __ldg(&bias[cg]); v1 += __ldg(&bias[cg + 1]); }
                v0 = fmaxf(v0, 0.f); v1 = fmaxf(v1, 0.f);
                *(__half2*)(Ch + (size_t)r * HH + cg) =
                    __floats2half2_rn(fminf(v0, 65504.f), fminf(v1, 65504.f));
                if (Cf) *(float2*)(Cf + (size_t)r * HH + cg) = make_float2(v0, v1);
            }
        }
    }
}

// ---------------------------------------------------------------------------
// CSR build
// ---------------------------------------------------------------------------
__global__ void hist_kernel(const int* __restrict__ erow, int* __restrict__ cnt, int E)
{
    for (int e = blockIdx.x * blockDim.x + threadIdx.x; e < E;
         e += gridDim.x * blockDim.x)
        atomicAdd(&cnt[__ldg(&erow[e])], 1);
}

__global__ __launch_bounds__(1024)
void scan_kernel(const int* __restrict__ cnt, int* __restrict__ rowptr)
{
    __shared__ int warpsums[32];
    __shared__ int running;
    int tid = threadIdx.x, lane = tid & 31, wid = tid >> 5;
    if (tid == 0) running = 0;
    __syncthreads();
    for (int base = 0; base < NN; base += 1024) {
        int v = (base + tid < NN) ? cnt[base + tid] : 0;
        int x = v;
#pragma unroll
        for (int o = 1; o < 32; o <<= 1) {
            int t = __shfl_up_sync(0xffffffffu, x, o);
            if (lane >= o) x += t;
        }
        if (lane == 31) warpsums[wid] = x;
        __syncthreads();
        if (wid == 0) {
            int s = warpsums[lane];
#pragma unroll
            for (int o = 1; o < 32; o <<= 1) {
                int t = __shfl_up_sync(0xffffffffu, s, o);
                if (lane >= o) s += t;
            }
            warpsums[lane] = s;
        }
        __syncthreads();
        int incl = x + (wid > 0 ? warpsums[wid - 1] : 0) + running;
        if (base + tid < NN) rowptr[base + tid + 1] = incl;
        __syncthreads();
        if (tid == 1023) running = incl;
        __syncthreads();
    }
    if (tid == 0) rowptr[0] = 0;
}

// csr_val folds (1-alpha) * SCL  (per-layer storage rescale, exact pow2)
__global__ void scatter_kernel(const int* __restrict__ erow,
                               const int* __restrict__ ecol,
                               const float* __restrict__ eval,
                               const int* __restrict__ rowptr,
                               int* __restrict__ cnt,
                               int* __restrict__ csr_col,
                               float* __restrict__ csr_val, int E)
{
    for (int e = blockIdx.x * blockDim.x + threadIdx.x; e < E;
         e += gridDim.x * blockDim.x) {
        int r = __ldg(&erow[e]);
        int p = __ldg(&rowptr[r]) + atomicAdd(&cnt[r], 1);
        csr_col[p] = __ldg(&ecol[e]);
        csr_val[p] = __ldg(&eval[e]) * ((1.0f - ALPHA) * SCL);
    }
}

// ---------------------------------------------------------------------------
// CSR SpMM, fp16 gather, fp32 accumulate. One warp per row; lane owns 8 ch.
// mix_scaled[r] = x0c*x0[r] + sum val' * h_scaled[col]   (x0c = alpha*s^{l+1})
// ---------------------------------------------------------------------------
__global__ __launch_bounds__(256)
void spmm_half_kernel(const int* __restrict__ rowptr,
                      const int* __restrict__ cols,
                      const float* __restrict__ vals,
                      const __half* __restrict__ h,
                      const float* __restrict__ x0,
                      float* __restrict__ mix, float x0c, int M)
{
    int row = (blockIdx.x * 256 + threadIdx.x) >> 5;
    int lane = threadIdx.x & 31;
    if (row >= M) return;

    int s = __ldg(&rowptr[row]);
    int e = __ldg(&rowptr[row + 1]);

    float acc[8];
    {
        float4 xa = __ldg((const float4*)(x0 + (size_t)row * HH) + lane * 2);
        float4 xb = __ldg((const float4*)(x0 + (size_t)row * HH) + lane * 2 + 1);
        acc[0] = x0c * xa.x; acc[1] = x0c * xa.y;
        acc[2] = x0c * xa.z; acc[3] = x0c * xa.w;
        acc[4] = x0c * xb.x; acc[5] = x0c * xb.y;
        acc[6] = x0c * xb.z; acc[7] = x0c * xb.w;
    }

    int i = s;
#define GATH(cc, vv) do {                                                  \
        uint4 q = __ldg((const uint4*)(h + (size_t)(cc) * HH) + lane);     \
        float2 f0 = __half22float2(*reinterpret_cast<__half2*>(&q.x));     \
        float2 f1 = __half22float2(*reinterpret_cast<__half2*>(&q.y));     \
        float2 f2 = __half22float2(*reinterpret_cast<__half2*>(&q.z));     \
        float2 f3 = __half22float2(*reinterpret_cast<__half2*>(&q.w));     \
        acc[0] += (vv) * f0.x; acc[1] += (vv) * f0.y;                      \
        acc[2] += (vv) * f1.x; acc[3] += (vv) * f1.y;                      \
        acc[4] += (vv) * f2.x; acc[5] += (vv) * f2.y;                      \
        acc[6] += (vv) * f3.x; acc[7] += (vv) * f3.y;                      \
    } while (0)

    for (; i + 4 <= e; i += 4) {
        int   c0 = __ldg(&cols[i]),     c1 = __ldg(&cols[i + 1]);
        int   c2 = __ldg(&cols[i + 2]), c3 = __ldg(&cols[i + 3]);
        float v0 = __ldg(&vals[i]),     v1 = __ldg(&vals[i + 1]);
        float v2 = __ldg(&vals[i + 2]), v3 = __ldg(&vals[i + 3]);
        GATH(c0, v0); GATH(c1, v1); GATH(c2, v2); GATH(c3, v3);
    }
    for (; i < e; i++) {
        int c = __ldg(&cols[i]);
        float v = __ldg(&vals[i]);
        GATH(c, v);
    }
#undef GATH

    float4* mp = (float4*)(mix + (size_t)row * HH);
    mp[lane * 2]     = make_float4(acc[0], acc[1], acc[2], acc[3]);
    mp[lane * 2 + 1] = make_float4(acc[4], acc[5], acc[6], acc[7]);
}

// ---------------------------------------------------------------------------
// Output head: logits = UNSCALE*(h_scaled @ W_out) + b, then log_softmax.
// ---------------------------------------------------------------------------
__global__ __launch_bounds__(256)
void out_kernel(const __half* __restrict__ h, const float* __restrict__ W,
                const float* __restrict__ b, float* __restrict__ out, int M)
{
    __shared__ float hs[8][HH];
    int tid = threadIdx.x;
    int warp = tid >> 5, lane = tid & 31;
    int row = blockIdx.x * 8 + warp;

    if (row < M) {
        const uint4* hp = (const uint4*)(h + (size_t)row * HH);
        uint4 q = __ldg(&hp[lane]);                 // 8 halfs
        float2 f0 = __half22float2(*reinterpret_cast<__half2*>(&q.x));
        float2 f1 = __half22float2(*reinterpret_cast<__half2*>(&q.y));
        float2 f2 = __half22float2(*reinterpret_cast<__half2*>(&q.z));
        float2 f3 = __half22float2(*reinterpret_cast<__half2*>(&q.w));
        int base = lane * 8;                        // 0..255
        hs[warp][base + 0] = f0.x; hs[warp][base + 1] = f0.y;
        hs[warp][base + 2] = f1.x; hs[warp][base + 3] = f1.y;
        hs[warp][base + 4] = f2.x; hs[warp][base + 5] = f2.y;
        hs[warp][base + 6] = f3.x; hs[warp][base + 7] = f3.y;
    }
    __syncthreads();
    if (row >= M) return;

    float l0 = 0.f, l1 = 0.f;
#pragma unroll 8
    for (int k = 0; k < HH; k++) {
        float hv = hs[warp][k];
        l0 += hv * __ldg(&W[k * CC + lane]);
        l1 += hv * __ldg(&W[k * CC + lane + 32]);
    }
    l0 = l0 * UNSCALE + __ldg(&b[lane]);
    l1 = l1 * UNSCALE + __ldg(&b[lane + 32]);
    float m = fmaxf(l0, l1);
#pragma unroll
    for (int o = 16; o; o >>= 1) m = fmaxf(m, __shfl_xor_sync(0xffffffffu, m, o));
    float s = expf(l0 - m) + expf(l1 - m);
#pragma unroll
    for (int o = 16; o; o >>= 1) s += __shfl_xor_sync(0xffffffffu, s, o);
    float lse = m + logf(s);
    out[(size_t)row * CC + lane] = l0 - lse;
    out[(size_t)row * CC + lane + 32] = l1 - lse;
}

// ---------------------------------------------------------------------------
extern "C" void kernel_launch(void* const* d_in, const int* in_sizes, int n_in,
                              void* d_out, int out_size)
{
    const float* x        = (const float*)d_in[0];
    const float* edge_val = (const float*)d_in[1];
    const float* W_in     = (const float*)d_in[2];
    const float* b_in     = (const float*)d_in[3];
    const float* conv_W   = (const float*)d_in[4];
    const float* W_out    = (const float*)d_in[5];
    const float* b_out    = (const float*)d_in[6];
    const int*   erow     = (const int*)d_in[7];
    const int*   ecol     = (const int*)d_in[8];
    float* out = (float*)d_out;

    float *x0, *agg, *csr_val;
    __half* hh;
    int *rowptr, *cnt, *csr_col;
    uint16_t *Bh, *Bl;
    cudaGetSymbolAddress((void**)&hh,      g_hh);
    cudaGetSymbolAddress((void**)&x0,      g_x0);
    cudaGetSymbolAddress((void**)&agg,     g_agg);
    cudaGetSymbolAddress((void**)&rowptr,  g_rowptr);
    cudaGetSymbolAddress((void**)&cnt,     g_cnt);
    cudaGetSymbolAddress((void**)&csr_col, g_col);
    cudaGetSymbolAddress((void**)&csr_val, g_val);
    cudaGetSymbolAddress((void**)&Bh,      g_Bh);
    cudaGetSymbolAddress((void**)&Bl,      g_Bl);

    const int smem_bytes = 4 * SA_ELEMS * sizeof(uint16_t);   // 73728
    cudaFuncSetAttribute(mma_gemm,
                         cudaFuncAttributeMaxDynamicSharedMemorySize, smem_bytes);

    dim3 gemm_grid(2, (NN + 127) / 128);

    // ---- B library + CSR build (per replay, deterministic) ----
    prep_B_kernel<<<(NCHUNKS_TOT * CHUNK_ELEMS + 255) / 256, 256>>>(
        W_in, conv_W, Bh, Bl);
    cudaMemsetAsync(cnt, 0, NN * sizeof(int));
    hist_kernel<<<592, 256>>>(erow, cnt, EE);
    scan_kernel<<<1, 1024>>>(cnt, rowptr);
    cudaMemsetAsync(cnt, 0, NN * sizeof(int));
    scatter_kernel<<<592, 256>>>(erow, ecol, edge_val, rowptr, cnt,
                                 csr_col, csr_val, EE);

    // ---- h0(half, scale s^0=1) = relu(x @ W_in + b_in); x0(fp32) dual ----
    mma_gemm<<<gemm_grid, 256, smem_bytes>>>(x, Bh, Bl, 0, 8, FIN,
                                             b_in, hh, x0, NN);

    for (int l = 0; l < LL; l++) {
        // mix_scaled = alpha*s^{l+1}*x0 + (0.9*s)*A @ h_scaled
        float x0c = ALPHA * ldexpf(1.0f, -4 * (l + 1));   // exact pow2
        spmm_half_kernel<<<(NN * 32 + 255) / 256, 256>>>(rowptr, csr_col,
                                                         csr_val, hh, x0,
                                                         agg, x0c, NN);
        // h_scaled = relu( mix_scaled @ ((1-beta)I + beta*W_l) )
        mma_gemm<<<gemm_grid, 256, smem_bytes>>>(agg, Bh, Bl, 8 + 4 * l, 4, HH,
                                                 nullptr, hh, nullptr, NN);
    }

    out_kernel<<<(NN + 7) / 8, 256>>>(hh, W_out, b_out, out, NN);
}